// round 2
// baseline (speedup 1.0000x reference)
#include <cuda_runtime.h>
#include <cstdint>
#include <climits>

#define B     4
#define NLID  16384
#define NIMG  4096
#define NTOK  20480
#define C     256
#define NV    6
#define TOTAL (B*NTOK)
#define NTHR  1024
#define NWARP 32
#define ITEMS 20            // NTOK / NTHR

// ---------------- static device scratch (no allocations) ----------------
__device__ unsigned long long g_e0[TOTAL];
__device__ unsigned long long g_e1[TOTAL];
__device__ unsigned int       g_qp[TOTAL];

// ---------------- dynamic shared layout (bytes) ----------------
#define SM_SRANK 0
#define SM_WHIST (SM_SRANK + NTOK*2)            // 40960
#define SM_BINB  (SM_WHIST + NWARP*256*4)       // 73728
#define SM_INVK  (SM_BINB  + 256*4)             // 74752
#define SM_INVR  (SM_INVK  + NV*9*4)
#define SM_MIN   (SM_INVR  + NV*9*4)
#define SM_MAX   (SM_MIN   + 3*4)
#define SM_BYTES (SM_MAX   + 3*4 + 64)

// ---------------- 3x3 inverse via adjugate in double ----------------
__device__ __forceinline__ void inv3(const float* a, float* o) {
    double m[9];
#pragma unroll
    for (int i = 0; i < 9; i++) m[i] = (double)a[i];
    double c00 =   m[4]*m[8] - m[5]*m[7];
    double c01 = -(m[3]*m[8] - m[5]*m[6]);
    double c02 =   m[3]*m[7] - m[4]*m[6];
    double det = m[0]*c00 + m[1]*c01 + m[2]*c02;
    double id  = 1.0 / det;
    o[0] = (float)( c00 * id);
    o[1] = (float)(-(m[1]*m[8] - m[2]*m[7]) * id);
    o[2] = (float)( (m[1]*m[5] - m[2]*m[4]) * id);
    o[3] = (float)( c01 * id);
    o[4] = (float)( (m[0]*m[8] - m[2]*m[6]) * id);
    o[5] = (float)(-(m[0]*m[5] - m[2]*m[3]) * id);
    o[6] = (float)( c02 * id);
    o[7] = (float)(-(m[0]*m[7] - m[1]*m[6]) * id);
    o[8] = (float)( (m[0]*m[4] - m[1]*m[3]) * id);
}

// ---------------- one stable 8-bit LSD radix pass (CTA-wide, 20480 items) ----------------
__device__ __forceinline__ void radix_pass(
    const unsigned long long* __restrict__ src,
    unsigned long long* __restrict__ dst,
    int shift, unsigned char* smem, int w, int lane, int tid)
{
    unsigned short* srank = (unsigned short*)(smem + SM_SRANK);
    unsigned int*   whist = (unsigned int*)(smem + SM_WHIST);
    unsigned int*   binb  = (unsigned int*)(smem + SM_BINB);

    __syncthreads();                       // prior pass's global writes visible
    for (int k = tid; k < NWARP * 256; k += NTHR) whist[k] = 0;
    __syncthreads();

    // ---- ranking: per-warp stable order via match_any ----
#pragma unroll
    for (int it = 0; it < ITEMS; it++) {
        int i = w * (ITEMS * 32) + it * 32 + lane;
        unsigned long long e = src[i];
        unsigned d = (unsigned)(e >> shift) & 255u;
        unsigned mset = __match_any_sync(0xFFFFFFFFu, d);
        unsigned before = whist[w * 256 + d];
        srank[i] = (unsigned short)(before + __popc(mset & ((1u << lane) - 1u)));
        __syncwarp();
        if ((mset & (0u - mset)) == (1u << lane))         // lowest-lane leader
            whist[w * 256 + d] = before + __popc(mset);
        __syncwarp();
    }
    __syncthreads();

    // ---- per-digit: exclusive over warps; totals -> binb ----
    if (tid < 256) {
        unsigned run = 0;
#pragma unroll 4
        for (int ww = 0; ww < NWARP; ww++) {
            unsigned t = whist[ww * 256 + tid];
            whist[ww * 256 + tid] = run;
            run += t;
        }
        binb[tid] = run;
    }
    __syncthreads();

    // ---- exclusive scan of 256 digit totals (warp 0) ----
    if (w == 0) {
        unsigned x[8], tot = 0;
#pragma unroll
        for (int k = 0; k < 8; k++) x[k] = binb[lane * 8 + k];
#pragma unroll
        for (int k = 0; k < 8; k++) { unsigned t = x[k]; x[k] = tot; tot += t; }
        unsigned s = tot;
#pragma unroll
        for (int off = 1; off < 32; off <<= 1) {
            unsigned n = __shfl_up_sync(0xFFFFFFFFu, s, off);
            if (lane >= off) s += n;
        }
        unsigned ex = s - tot;
#pragma unroll
        for (int k = 0; k < 8; k++) binb[lane * 8 + k] = ex + x[k];
    }
    __syncthreads();

    // ---- scatter ----
#pragma unroll
    for (int it = 0; it < ITEMS; it++) {
        int i = w * (ITEMS * 32) + it * 32 + lane;
        unsigned long long e = src[i];
        unsigned d = (unsigned)(e >> shift) & 255u;
        unsigned pos = binb[d] + whist[w * 256 + d] + srank[i];
        dst[pos] = e;
    }
}

// ---------------- fused: inverses + unproject + quantize + minmax + keys + 3-pass sort ----------------
extern "C" __global__ void __launch_bounds__(NTHR, 1) fused_kernel(
    const float* __restrict__ lidar_coords,
    const float* __restrict__ img_kuvd,
    const float* __restrict__ Kmat,
    const float* __restrict__ Tmat,
    const float* __restrict__ Rmat,
    const float* __restrict__ ptrans,
    const unsigned char* __restrict__ lmask,
    const unsigned char* __restrict__ imask)
{
    extern __shared__ unsigned char smem[];
    int b = blockIdx.x;
    int tid = threadIdx.x;
    int w = tid >> 5, lane = tid & 31;

    float* sInvK = (float*)(smem + SM_INVK);
    float* sInvR = (float*)(smem + SM_INVR);
    int*   smin  = (int*)(smem + SM_MIN);
    int*   smax  = (int*)(smem + SM_MAX);

    if (tid < 3) { smin[tid] = INT_MAX; smax[tid] = INT_MIN; }
    if (tid < NV) {
        inv3(Kmat + ((size_t)b * NV + tid) * 9, sInvK + tid * 9);
        inv3(Rmat + ((size_t)b * NV + tid) * 9, sInvR + tid * 9);
    }
    __syncthreads();

    // ---- phase 1: coords -> quantized cells, per-batch min/max ----
    int mn0 = INT_MAX, mn1 = INT_MAX, mn2 = INT_MAX;
    int mx0 = INT_MIN, mx1 = INT_MIN, mx2 = INT_MIN;
#pragma unroll
    for (int it = 0; it < ITEMS; it++) {
        int i = w * (ITEMS * 32) + it * 32 + lane;
        float x, y, z;
        if (i < NLID) {
            const float* c = lidar_coords + ((size_t)b * NLID + i) * 3;
            x = c[0]; y = c[1]; z = c[2];
        } else {
            int j = i - NLID;
            const float* kv = img_kuvd + ((size_t)b * NIMG + j) * 4;
            int cam = (int)kv[0];
            float u = kv[1], v = kv[2], D = kv[3];
            const float* tt = ptrans + (b * NV + cam) * 3;
            float u1 = u - tt[0], v1 = v - tt[1], w1 = 1.0f - tt[2];
            const float* iR = sInvR + cam * 9;
            float rx = fmaf(iR[0], u1, fmaf(iR[1], v1, iR[2] * w1));
            float ry = fmaf(iR[3], u1, fmaf(iR[4], v1, iR[5] * w1));
            const float* iK = sInvK + cam * 9;
            float cx = fmaf(iK[0], rx, fmaf(iK[1], ry, iK[2])) * D;
            float cy = fmaf(iK[3], rx, fmaf(iK[4], ry, iK[5])) * D;
            float cz = fmaf(iK[6], rx, fmaf(iK[7], ry, iK[8])) * D;
            const float* Tm = Tmat + (size_t)(b * NV + cam) * 16;
            x = fmaf(Tm[0], cx, fmaf(Tm[1], cy, fmaf(Tm[2],  cz, Tm[3])));
            y = fmaf(Tm[4], cx, fmaf(Tm[5], cy, fmaf(Tm[6],  cz, Tm[7])));
            z = fmaf(Tm[8], cx, fmaf(Tm[9], cy, fmaf(Tm[10], cz, Tm[11])));
        }
        int q0 = (int)floorf(x), q1 = (int)floorf(y), q2 = (int)floorf(z);
        g_qp[b * NTOK + i] = ((unsigned)(q0 + 256) << 20) |
                             ((unsigned)(q1 + 256) << 10) |
                              (unsigned)(q2 + 256);
        mn0 = min(mn0, q0); mx0 = max(mx0, q0);
        mn1 = min(mn1, q1); mx1 = max(mx1, q1);
        mn2 = min(mn2, q2); mx2 = max(mx2, q2);
    }
#pragma unroll
    for (int off = 16; off; off >>= 1) {
        mn0 = min(mn0, __shfl_xor_sync(0xFFFFFFFFu, mn0, off));
        mn1 = min(mn1, __shfl_xor_sync(0xFFFFFFFFu, mn1, off));
        mn2 = min(mn2, __shfl_xor_sync(0xFFFFFFFFu, mn2, off));
        mx0 = max(mx0, __shfl_xor_sync(0xFFFFFFFFu, mx0, off));
        mx1 = max(mx1, __shfl_xor_sync(0xFFFFFFFFu, mx1, off));
        mx2 = max(mx2, __shfl_xor_sync(0xFFFFFFFFu, mx2, off));
    }
    if (lane == 0) {
        atomicMin(&smin[0], mn0); atomicMax(&smax[0], mx0);
        atomicMin(&smin[1], mn1); atomicMax(&smax[1], mx1);
        atomicMin(&smin[2], mn2); atomicMax(&smax[2], mx2);
    }
    __syncthreads();

    // ---- phase 2: snake keys ----
    int m0 = smin[0], m1 = smin[1], m2 = smin[2];
    int M1 = smax[1] - m1, M2 = smax[2] - m2;
#pragma unroll
    for (int it = 0; it < ITEMS; it++) {
        int i = w * (ITEMS * 32) + it * 32 + lane;
        unsigned qp = g_qp[b * NTOK + i];
        int q0 = (int)((qp >> 20) & 1023u) - 256;
        int q1 = (int)((qp >> 10) & 1023u) - 256;
        int q2 = (int)( qp        & 1023u) - 256;
        int d0 = q0 - m0, d1 = q1 - m1, d2 = q2 - m2;
        int s1 = (d0 & 1)        ? (M1 - d1) : d1;
        int s2 = ((d0 + d1) & 1) ? (M2 - d2) : d2;
        bool msk = (i < NLID) ? (lmask[(size_t)b * NLID + i] != 0)
                              : (imask[(size_t)b * NIMG + (i - NLID)] != 0);
        unsigned key = msk ? 0xFFFFFFu
                           : (((unsigned)d0 << 16) | ((unsigned)s1 << 8) | (unsigned)s2);
        g_e0[b * NTOK + i] = ((unsigned long long)key << 16) | (unsigned)i;
    }

    // ---- phase 3: 3 stable radix passes over key bits [16,40) ----
    const int seg = b * NTOK;
    radix_pass(g_e0 + seg, g_e1 + seg, 16, smem, w, lane, tid);
    radix_pass(g_e1 + seg, g_e0 + seg, 24, smem, w, lane, tid);
    radix_pass(g_e0 + seg, g_e1 + seg, 32, smem, w, lane, tid);
}

// ---------------- gather rows + idx/mask + trailing scalars ----------------
__global__ void gather_kernel(const float* __restrict__ lidar_tokens,
                              const float* __restrict__ img_tokens,
                              const unsigned char* __restrict__ lmask,
                              const unsigned char* __restrict__ imask,
                              float* __restrict__ out) {
    long long gid = (long long)blockIdx.x * blockDim.x + threadIdx.x;
    int r  = (int)(gid >> 6);
    int c4 = (int)(gid & 63);
    if (r >= TOTAL) return;
    unsigned long long e = g_e1[r];
    int idx = (int)(e & 0xFFFFull);
    int b = r / NTOK;
    const float4* src;
    if (idx < NLID)
        src = (const float4*)(lidar_tokens + ((size_t)b * NLID + idx) * C);
    else
        src = (const float4*)(img_tokens + ((size_t)b * NIMG + (idx - NLID)) * C);
    ((float4*)out)[(size_t)r * 64 + c4] = src[c4];

    if (c4 == 0) {
        size_t idx_base  = (size_t)TOTAL * C;
        size_t mask_base = idx_base + TOTAL;
        out[idx_base + r] = (float)idx;
        bool m = (idx < NLID) ? (lmask[(size_t)b * NLID + idx] != 0)
                              : (imask[(size_t)b * NIMG + (idx - NLID)] != 0);
        out[mask_base + r] = m ? 1.0f : 0.0f;
        if (r == 0) {
            out[mask_base + TOTAL + 0] = 16384.0f;
            out[mask_base + TOTAL + 1] = 1.0f;
        }
    }
}

// ---------------- launch ----------------
extern "C" void kernel_launch(void* const* d_in, const int* in_sizes, int n_in,
                              void* d_out, int out_size) {
    const float* lidar_tokens = (const float*)d_in[0];
    const float* lidar_coords = (const float*)d_in[1];
    const float* img_tokens   = (const float*)d_in[2];
    const float* img_kuvd     = (const float*)d_in[3];
    const float* Km           = (const float*)d_in[4];
    const float* Tm           = (const float*)d_in[5];
    const float* Rm           = (const float*)d_in[6];
    const float* ptrans       = (const float*)d_in[7];
    const unsigned char* lm   = (const unsigned char*)d_in[8];
    const unsigned char* im   = (const unsigned char*)d_in[9];
    float* out = (float*)d_out;

    cudaFuncSetAttribute(fused_kernel,
                         cudaFuncAttributeMaxDynamicSharedMemorySize, SM_BYTES);

    fused_kernel<<<B, NTHR, SM_BYTES>>>(lidar_coords, img_kuvd, Km, Tm, Rm,
                                        ptrans, lm, im);
    gather_kernel<<<(TOTAL * 64) / 256, 256>>>(lidar_tokens, img_tokens, lm, im, out);
}

// round 3
// speedup vs baseline: 1.0892x; 1.0892x over previous
#include <cuda_runtime.h>
#include <cstdint>
#include <climits>

#define B     4
#define NLID  16384
#define NIMG  4096
#define NTOK  20480
#define C     256
#define NV    6
#define TOTAL (B*NTOK)
#define NTHR  1024
#define NWARP 32
#define ITEMS 20            // NTOK / NTHR

// ---------------- static device scratch (no allocations) ----------------
__device__ unsigned long long g_e0[TOTAL];
__device__ unsigned long long g_e1[TOTAL];
__device__ int4               g_q[TOTAL];
__device__ int                g_min[B][3];
__device__ int                g_max[B][3];
__device__ float              g_invK[B][NV][9];
__device__ float              g_invR[B][NV][9];

// ---------------- sort kernel shared layout (bytes) ----------------
#define SM_SRANK 0
#define SM_WHIST (SM_SRANK + NTOK*2)            // 40960
#define SM_BINB  (SM_WHIST + NWARP*256*4)       // 73728
#define SM_BYTES (SM_BINB  + 256*4)             // 74752

// ---------------- 3x3 inverse via adjugate in double ----------------
__device__ __forceinline__ void inv3(const float* a, float* o) {
    double m[9];
#pragma unroll
    for (int i = 0; i < 9; i++) m[i] = (double)a[i];
    double c00 =   m[4]*m[8] - m[5]*m[7];
    double c01 = -(m[3]*m[8] - m[5]*m[6]);
    double c02 =   m[3]*m[7] - m[4]*m[6];
    double det = m[0]*c00 + m[1]*c01 + m[2]*c02;
    double id  = 1.0 / det;
    o[0] = (float)( c00 * id);
    o[1] = (float)(-(m[1]*m[8] - m[2]*m[7]) * id);
    o[2] = (float)( (m[1]*m[5] - m[2]*m[4]) * id);
    o[3] = (float)( c01 * id);
    o[4] = (float)( (m[0]*m[8] - m[2]*m[6]) * id);
    o[5] = (float)(-(m[0]*m[5] - m[2]*m[3]) * id);
    o[6] = (float)( c02 * id);
    o[7] = (float)(-(m[0]*m[7] - m[1]*m[6]) * id);
    o[8] = (float)( (m[0]*m[4] - m[1]*m[3]) * id);
}

// ---------------- setup: inverses + minmax identities + trailing scalars ----------------
__global__ void setup_kernel(const float* __restrict__ K, const float* __restrict__ R,
                             float* out, int out_size) {
    int t = threadIdx.x;
    if (t < B * 3) {
        ((int*)g_min)[t] = INT_MAX;
        ((int*)g_max)[t] = INT_MIN;
    }
    if (t < B * NV) {
        int b = t / NV, v = t % NV;
        inv3(K + (size_t)t * 9, g_invK[b][v]);
        inv3(R + (size_t)t * 9, g_invR[b][v]);
    }
    if (t == 0) {
        size_t base = (size_t)TOTAL * C + 2 * (size_t)TOTAL;
        if ((size_t)out_size >= base + 2) {
            out[base + 0] = 16384.0f;
            out[base + 1] = 1.0f;
        }
    }
}

// ---------------- quantize + per-batch min/max (wide grid) ----------------
__global__ void q_kernel(const float* __restrict__ lidar_coords,
                         const float* __restrict__ img_kuvd,
                         const float* __restrict__ T,
                         const float* __restrict__ post_trans) {
    int b = blockIdx.y;
    int i = blockIdx.x * blockDim.x + threadIdx.x;   // < NTOK

    float x, y, z;
    if (i < NLID) {
        const float* c = lidar_coords + ((size_t)b * NLID + i) * 3;
        x = c[0]; y = c[1]; z = c[2];
    } else {
        int j = i - NLID;
        const float* kv = img_kuvd + ((size_t)b * NIMG + j) * 4;
        int cam = (int)kv[0];
        float u = kv[1], v = kv[2], D = kv[3];
        const float* tt = post_trans + (b * NV + cam) * 3;
        float u1 = u - tt[0], v1 = v - tt[1], w1 = 1.0f - tt[2];
        const float* iR = g_invR[b][cam];
        float rx = fmaf(iR[0], u1, fmaf(iR[1], v1, iR[2] * w1));
        float ry = fmaf(iR[3], u1, fmaf(iR[4], v1, iR[5] * w1));
        const float* iK = g_invK[b][cam];
        float cx = fmaf(iK[0], rx, fmaf(iK[1], ry, iK[2])) * D;
        float cy = fmaf(iK[3], rx, fmaf(iK[4], ry, iK[5])) * D;
        float cz = fmaf(iK[6], rx, fmaf(iK[7], ry, iK[8])) * D;
        const float* Tm = T + (size_t)(b * NV + cam) * 16;
        x = fmaf(Tm[0], cx, fmaf(Tm[1], cy, fmaf(Tm[2],  cz, Tm[3])));
        y = fmaf(Tm[4], cx, fmaf(Tm[5], cy, fmaf(Tm[6],  cz, Tm[7])));
        z = fmaf(Tm[8], cx, fmaf(Tm[9], cy, fmaf(Tm[10], cz, Tm[11])));
    }
    int q0 = (int)floorf(x), q1 = (int)floorf(y), q2 = (int)floorf(z);
    g_q[b * NTOK + i] = make_int4(q0, q1, q2, 0);

    __shared__ int smin[3], smax[3];
    if (threadIdx.x < 3) { smin[threadIdx.x] = INT_MAX; smax[threadIdx.x] = INT_MIN; }
    __syncthreads();
    atomicMin(&smin[0], q0); atomicMax(&smax[0], q0);
    atomicMin(&smin[1], q1); atomicMax(&smax[1], q1);
    atomicMin(&smin[2], q2); atomicMax(&smax[2], q2);
    __syncthreads();
    if (threadIdx.x < 3) {
        atomicMin(&g_min[b][threadIdx.x], smin[threadIdx.x]);
        atomicMax(&g_max[b][threadIdx.x], smax[threadIdx.x]);
    }
}

// ---------------- build compact 24-bit snake keys (wide grid) ----------------
// entry = key(24b) << 16 | idx(16b); per-CTA sort handles batch segmentation.
__global__ void key_kernel(const unsigned char* __restrict__ lmask,
                           const unsigned char* __restrict__ imask) {
    int gid = blockIdx.x * blockDim.x + threadIdx.x;
    if (gid >= TOTAL) return;
    int b = gid / NTOK, i = gid % NTOK;
    int4 q = g_q[gid];
    int m0 = g_min[b][0], m1 = g_min[b][1], m2 = g_min[b][2];
    int d0 = q.x - m0, d1 = q.y - m1, d2 = q.z - m2;
    int M1 = g_max[b][1] - m1;
    int M2 = g_max[b][2] - m2;
    int s1 = (d0 & 1)        ? (M1 - d1) : d1;
    int s2 = ((d0 + d1) & 1) ? (M2 - d2) : d2;
    bool msk = (i < NLID) ? (lmask[(size_t)b * NLID + i] != 0)
                          : (imask[(size_t)b * NIMG + (i - NLID)] != 0);
    unsigned key = msk ? 0xFFFFFFu
                       : (((unsigned)d0 << 16) | ((unsigned)s1 << 8) | (unsigned)s2);
    g_e0[gid] = ((unsigned long long)key << 16) | (unsigned)i;
}

// ---------------- one stable 8-bit LSD radix pass (CTA-wide, 20480 items) ----------------
__device__ __forceinline__ void radix_pass(
    const unsigned long long* __restrict__ src,
    unsigned long long* __restrict__ dst,
    int shift, unsigned char* smem, int w, int lane, int tid)
{
    unsigned short* srank = (unsigned short*)(smem + SM_SRANK);
    unsigned int*   whist = (unsigned int*)(smem + SM_WHIST);
    unsigned int*   binb  = (unsigned int*)(smem + SM_BINB);

    __syncthreads();
    for (int k = tid; k < NWARP * 256; k += NTHR) whist[k] = 0;
    __syncthreads();

    // ---- ranking: per-warp stable order via match_any ----
    for (int it = 0; it < ITEMS; it++) {
        int i = w * (ITEMS * 32) + it * 32 + lane;
        unsigned long long e = src[i];
        unsigned d = (unsigned)(e >> shift) & 255u;
        unsigned mset = __match_any_sync(0xFFFFFFFFu, d);
        unsigned before = whist[w * 256 + d];
        srank[i] = (unsigned short)(before + __popc(mset & ((1u << lane) - 1u)));
        __syncwarp();
        if ((mset & (0u - mset)) == (1u << lane))
            whist[w * 256 + d] = before + __popc(mset);
        __syncwarp();
    }
    __syncthreads();

    // ---- per-digit exclusive over warps; totals -> binb ----
    if (tid < 256) {
        unsigned run = 0;
        for (int ww = 0; ww < NWARP; ww++) {
            unsigned t = whist[ww * 256 + tid];
            whist[ww * 256 + tid] = run;
            run += t;
        }
        binb[tid] = run;
    }
    __syncthreads();

    // ---- exclusive scan of 256 digit totals (warp 0) ----
    if (w == 0) {
        unsigned x[8], tot = 0;
#pragma unroll
        for (int k = 0; k < 8; k++) x[k] = binb[lane * 8 + k];
#pragma unroll
        for (int k = 0; k < 8; k++) { unsigned t = x[k]; x[k] = tot; tot += t; }
        unsigned s = tot;
#pragma unroll
        for (int off = 1; off < 32; off <<= 1) {
            unsigned n = __shfl_up_sync(0xFFFFFFFFu, s, off);
            if (lane >= off) s += n;
        }
        unsigned ex = s - tot;
#pragma unroll
        for (int k = 0; k < 8; k++) binb[lane * 8 + k] = ex + x[k];
    }
    __syncthreads();

    // ---- scatter ----
    for (int it = 0; it < ITEMS; it++) {
        int i = w * (ITEMS * 32) + it * 32 + lane;
        unsigned long long e = src[i];
        unsigned d = (unsigned)(e >> shift) & 255u;
        unsigned pos = binb[d] + whist[w * 256 + d] + srank[i];
        dst[pos] = e;
    }
}

// ---------------- sort-only kernel: one CTA per batch, 3 passes ----------------
extern "C" __global__ void __launch_bounds__(NTHR, 1) sort_kernel() {
    extern __shared__ unsigned char smem[];
    int tid = threadIdx.x;
    int w = tid >> 5, lane = tid & 31;
    const int seg = blockIdx.x * NTOK;
    radix_pass(g_e0 + seg, g_e1 + seg, 16, smem, w, lane, tid);
    radix_pass(g_e1 + seg, g_e0 + seg, 24, smem, w, lane, tid);
    radix_pass(g_e0 + seg, g_e1 + seg, 32, smem, w, lane, tid);
}

// ---------------- gather rows + idx/mask outputs ----------------
__global__ void gather_kernel(const float* __restrict__ lidar_tokens,
                              const float* __restrict__ img_tokens,
                              const unsigned char* __restrict__ lmask,
                              const unsigned char* __restrict__ imask,
                              float* __restrict__ out) {
    long long gid = (long long)blockIdx.x * blockDim.x + threadIdx.x;
    int r  = (int)(gid >> 6);
    int c4 = (int)(gid & 63);
    if (r >= TOTAL) return;
    unsigned long long e = g_e1[r];
    int idx = (int)(e & 0xFFFFull);
    int b = r / NTOK;
    const float4* src;
    if (idx < NLID)
        src = (const float4*)(lidar_tokens + ((size_t)b * NLID + idx) * C);
    else
        src = (const float4*)(img_tokens + ((size_t)b * NIMG + (idx - NLID)) * C);
    ((float4*)out)[(size_t)r * 64 + c4] = src[c4];

    if (c4 == 0) {
        size_t idx_base  = (size_t)TOTAL * C;
        size_t mask_base = idx_base + TOTAL;
        out[idx_base + r] = (float)idx;
        bool m = (idx < NLID) ? (lmask[(size_t)b * NLID + idx] != 0)
                              : (imask[(size_t)b * NIMG + (idx - NLID)] != 0);
        out[mask_base + r] = m ? 1.0f : 0.0f;
    }
}

// ---------------- launch ----------------
extern "C" void kernel_launch(void* const* d_in, const int* in_sizes, int n_in,
                              void* d_out, int out_size) {
    const float* lidar_tokens = (const float*)d_in[0];
    const float* lidar_coords = (const float*)d_in[1];
    const float* img_tokens   = (const float*)d_in[2];
    const float* img_kuvd     = (const float*)d_in[3];
    const float* Km           = (const float*)d_in[4];
    const float* Tm           = (const float*)d_in[5];
    const float* Rm           = (const float*)d_in[6];
    const float* ptrans       = (const float*)d_in[7];
    const unsigned char* lm   = (const unsigned char*)d_in[8];
    const unsigned char* im   = (const unsigned char*)d_in[9];
    float* out = (float*)d_out;

    static bool attr_set = false;
    if (!attr_set) {
        cudaFuncSetAttribute(sort_kernel,
                             cudaFuncAttributeMaxDynamicSharedMemorySize, SM_BYTES);
        attr_set = true;
    }

    setup_kernel<<<1, 32>>>(Km, Rm, out, out_size);

    dim3 gq(NTOK / 256, B);
    q_kernel<<<gq, 256>>>(lidar_coords, img_kuvd, Tm, ptrans);

    key_kernel<<<(TOTAL + 255) / 256, 256>>>(lm, im);

    sort_kernel<<<B, NTHR, SM_BYTES>>>();

    gather_kernel<<<(TOTAL * 64) / 256, 256>>>(lidar_tokens, img_tokens, lm, im, out);
}

// round 4
// speedup vs baseline: 2.0338x; 1.8672x over previous
#include <cuda_runtime.h>
#include <cstdint>
#include <climits>

#define B        4
#define NLID     16384
#define NIMG     4096
#define NTOK     20480
#define C        256
#define NV       6
#define TOTAL    (B*NTOK)        // 81920
#define STHR     512             // sort-phase threads/block
#define SWARP    16              // warps per sort block
#define IPT      4               // items/thread
#define BLK_ITEMS (STHR*IPT)     // 2048
#define NBLK_SEG (NTOK/BLK_ITEMS)// 10
#define NBLKS    (B*NBLK_SEG)    // 40
#define CNT_SEG  (256*NBLK_SEG)  // 2560 counts per segment

// ---------------- static device scratch (no allocations) ----------------
__device__ unsigned long long g_e0[TOTAL];
__device__ unsigned long long g_e1[TOTAL];
__device__ int4               g_q[TOTAL];
__device__ unsigned int       g_cnt[B * CNT_SEG];
__device__ int                g_min[B][3];
__device__ int                g_max[B][3];
__device__ float              g_invK[B][NV][9];
__device__ float              g_invR[B][NV][9];

// ---------------- 3x3 inverse via adjugate in double ----------------
__device__ __forceinline__ void inv3(const float* a, float* o) {
    double m[9];
#pragma unroll
    for (int i = 0; i < 9; i++) m[i] = (double)a[i];
    double c00 =   m[4]*m[8] - m[5]*m[7];
    double c01 = -(m[3]*m[8] - m[5]*m[6]);
    double c02 =   m[3]*m[7] - m[4]*m[6];
    double det = m[0]*c00 + m[1]*c01 + m[2]*c02;
    double id  = 1.0 / det;
    o[0] = (float)( c00 * id);
    o[1] = (float)(-(m[1]*m[8] - m[2]*m[7]) * id);
    o[2] = (float)( (m[1]*m[5] - m[2]*m[4]) * id);
    o[3] = (float)( c01 * id);
    o[4] = (float)( (m[0]*m[8] - m[2]*m[6]) * id);
    o[5] = (float)(-(m[0]*m[5] - m[2]*m[3]) * id);
    o[6] = (float)( c02 * id);
    o[7] = (float)(-(m[0]*m[7] - m[1]*m[6]) * id);
    o[8] = (float)( (m[0]*m[4] - m[1]*m[3]) * id);
}

// ---------------- setup ----------------
__global__ void setup_kernel(const float* __restrict__ K, const float* __restrict__ R,
                             float* out, int out_size) {
    int t = threadIdx.x;
    if (t < B * 3) {
        ((int*)g_min)[t] = INT_MAX;
        ((int*)g_max)[t] = INT_MIN;
    }
    if (t < B * NV) {
        int b = t / NV, v = t % NV;
        inv3(K + (size_t)t * 9, g_invK[b][v]);
        inv3(R + (size_t)t * 9, g_invR[b][v]);
    }
    if (t == 0) {
        size_t base = (size_t)TOTAL * C + 2 * (size_t)TOTAL;
        if ((size_t)out_size >= base + 2) {
            out[base + 0] = 16384.0f;
            out[base + 1] = 1.0f;
        }
    }
}

// ---------------- quantize + per-batch min/max ----------------
__global__ void q_kernel(const float* __restrict__ lidar_coords,
                         const float* __restrict__ img_kuvd,
                         const float* __restrict__ T,
                         const float* __restrict__ post_trans) {
    int b = blockIdx.y;
    int i = blockIdx.x * blockDim.x + threadIdx.x;

    float x, y, z;
    if (i < NLID) {
        const float* c = lidar_coords + ((size_t)b * NLID + i) * 3;
        x = c[0]; y = c[1]; z = c[2];
    } else {
        int j = i - NLID;
        const float* kv = img_kuvd + ((size_t)b * NIMG + j) * 4;
        int cam = (int)kv[0];
        float u = kv[1], v = kv[2], D = kv[3];
        const float* tt = post_trans + (b * NV + cam) * 3;
        float u1 = u - tt[0], v1 = v - tt[1], w1 = 1.0f - tt[2];
        const float* iR = g_invR[b][cam];
        float rx = fmaf(iR[0], u1, fmaf(iR[1], v1, iR[2] * w1));
        float ry = fmaf(iR[3], u1, fmaf(iR[4], v1, iR[5] * w1));
        const float* iK = g_invK[b][cam];
        float cx = fmaf(iK[0], rx, fmaf(iK[1], ry, iK[2])) * D;
        float cy = fmaf(iK[3], rx, fmaf(iK[4], ry, iK[5])) * D;
        float cz = fmaf(iK[6], rx, fmaf(iK[7], ry, iK[8])) * D;
        const float* Tm = T + (size_t)(b * NV + cam) * 16;
        x = fmaf(Tm[0], cx, fmaf(Tm[1], cy, fmaf(Tm[2],  cz, Tm[3])));
        y = fmaf(Tm[4], cx, fmaf(Tm[5], cy, fmaf(Tm[6],  cz, Tm[7])));
        z = fmaf(Tm[8], cx, fmaf(Tm[9], cy, fmaf(Tm[10], cz, Tm[11])));
    }
    int q0 = (int)floorf(x), q1 = (int)floorf(y), q2 = (int)floorf(z);
    g_q[b * NTOK + i] = make_int4(q0, q1, q2, 0);

    __shared__ int smin[3], smax[3];
    if (threadIdx.x < 3) { smin[threadIdx.x] = INT_MAX; smax[threadIdx.x] = INT_MIN; }
    __syncthreads();
    atomicMin(&smin[0], q0); atomicMax(&smax[0], q0);
    atomicMin(&smin[1], q1); atomicMax(&smax[1], q1);
    atomicMin(&smin[2], q2); atomicMax(&smax[2], q2);
    __syncthreads();
    if (threadIdx.x < 3) {
        atomicMin(&g_min[b][threadIdx.x], smin[threadIdx.x]);
        atomicMax(&g_max[b][threadIdx.x], smax[threadIdx.x]);
    }
}

// ---------------- pass 0: build keys + per-block histogram (digit = bits[16,24)) ----------------
__global__ void key_hist_kernel(const unsigned char* __restrict__ lmask,
                                const unsigned char* __restrict__ imask) {
    __shared__ unsigned hist[256];
    int tid = threadIdx.x;
    if (tid < 256) hist[tid] = 0;
    __syncthreads();

    int blk = blockIdx.x, seg = blk / NBLK_SEG, bib = blk % NBLK_SEG;
    int base = seg * NTOK + bib * BLK_ITEMS;
    int m0 = g_min[seg][0], m1 = g_min[seg][1], m2 = g_min[seg][2];
    int M1 = g_max[seg][1] - m1, M2 = g_max[seg][2] - m2;

#pragma unroll
    for (int k = 0; k < IPT; k++) {
        int gid = base + tid + k * STHR;
        int i = gid - seg * NTOK;
        int4 q = g_q[gid];
        int d0 = q.x - m0, d1 = q.y - m1, d2 = q.z - m2;
        int s1 = (d0 & 1)        ? (M1 - d1) : d1;
        int s2 = ((d0 + d1) & 1) ? (M2 - d2) : d2;
        bool msk = (i < NLID) ? (lmask[(size_t)seg * NLID + i] != 0)
                              : (imask[(size_t)seg * NIMG + (i - NLID)] != 0);
        unsigned key = msk ? 0xFFFFFFu
                           : (((unsigned)d0 << 16) | ((unsigned)s1 << 8) | (unsigned)s2);
        g_e0[gid] = ((unsigned long long)key << 16) | (unsigned)i;
        atomicAdd(&hist[key & 255u], 1u);
    }
    __syncthreads();
    if (tid < 256)
        g_cnt[seg * CNT_SEG + tid * NBLK_SEG + bib] = hist[tid];
}

// ---------------- histogram for later passes ----------------
__global__ void hist_kernel(const unsigned long long* __restrict__ src, int shift) {
    __shared__ unsigned hist[256];
    int tid = threadIdx.x;
    if (tid < 256) hist[tid] = 0;
    __syncthreads();
    int blk = blockIdx.x, seg = blk / NBLK_SEG, bib = blk % NBLK_SEG;
    const unsigned long long* s = src + seg * NTOK + bib * BLK_ITEMS;
#pragma unroll
    for (int k = 0; k < IPT; k++) {
        unsigned d = (unsigned)(s[tid + k * STHR] >> shift) & 255u;
        atomicAdd(&hist[d], 1u);
    }
    __syncthreads();
    if (tid < 256)
        g_cnt[seg * CNT_SEG + tid * NBLK_SEG + bib] = hist[tid];
}

// ---------------- per-segment exclusive scan over 2560 counts (digit-major, block) ----------------
__global__ void scan_kernel() {
    int seg = blockIdx.x;
    unsigned* cnt = g_cnt + seg * CNT_SEG;
    int tid = threadIdx.x;              // 512 threads, 5 entries each
    int lane = tid & 31, w = tid >> 5;  // 16 warps

    unsigned v[5];
#pragma unroll
    for (int k = 0; k < 5; k++) v[k] = cnt[tid * 5 + k];
    unsigned sum = 0;
#pragma unroll
    for (int k = 0; k < 5; k++) { unsigned t = v[k]; v[k] = sum; sum += t; }

    unsigned s = sum;
#pragma unroll
    for (int off = 1; off < 32; off <<= 1) {
        unsigned n = __shfl_up_sync(0xFFFFFFFFu, s, off);
        if (lane >= off) s += n;
    }
    __shared__ unsigned wsum[SWARP];
    if (lane == 31) wsum[w] = s;
    __syncthreads();
    if (tid == 0) {
        unsigned run = 0;
#pragma unroll
        for (int i = 0; i < SWARP; i++) { unsigned t = wsum[i]; wsum[i] = run; run += t; }
    }
    __syncthreads();
    unsigned ex = wsum[w] + (s - sum);
#pragma unroll
    for (int k = 0; k < 5; k++) cnt[tid * 5 + k] = ex + v[k];
}

// ---------------- stable scatter ----------------
__global__ void __launch_bounds__(STHR) scatter_kernel(
    const unsigned long long* __restrict__ src,
    unsigned long long* __restrict__ dst, int shift)
{
    __shared__ unsigned base[256];
    __shared__ unsigned whist[SWARP][256];
    int tid = threadIdx.x;
    int lane = tid & 31, w = tid >> 5;
    int blk = blockIdx.x, seg = blk / NBLK_SEG, bib = blk % NBLK_SEG;

    if (tid < 256) base[tid] = g_cnt[seg * CNT_SEG + tid * NBLK_SEG + bib];
#pragma unroll
    for (int k = 0; k < (SWARP * 256) / STHR; k++)
        ((unsigned*)whist)[tid + k * STHR] = 0;
    __syncthreads();

    const unsigned long long* s = src + seg * NTOK + bib * BLK_ITEMS;

    // items: i = w*128 + it*32 + lane  (ascending (w, it, lane) == memory order)
    unsigned long long e[IPT];
    unsigned dg[IPT], rk[IPT];
#pragma unroll
    for (int it = 0; it < IPT; it++) {
        int i = w * (IPT * 32) + it * 32 + lane;
        e[it]  = s[i];
        dg[it] = (unsigned)(e[it] >> shift) & 255u;
        unsigned mset = __match_any_sync(0xFFFFFFFFu, dg[it]);
        unsigned before = whist[w][dg[it]];
        rk[it] = before + __popc(mset & ((1u << lane) - 1u));
        __syncwarp();
        if ((mset & (0u - mset)) == (1u << lane))
            whist[w][dg[it]] = before + __popc(mset);
        __syncwarp();
    }
    __syncthreads();

    // exclusive over warps per digit
    if (tid < 256) {
        unsigned run = 0;
#pragma unroll
        for (int ww = 0; ww < SWARP; ww++) {
            unsigned t = whist[ww][tid];
            whist[ww][tid] = run;
            run += t;
        }
    }
    __syncthreads();

    unsigned long long* d = dst + seg * NTOK;
#pragma unroll
    for (int it = 0; it < IPT; it++) {
        unsigned pos = base[dg[it]] + whist[w][dg[it]] + rk[it];
        d[pos] = e[it];
    }
}

// ---------------- gather rows + idx/mask outputs ----------------
__global__ void gather_kernel(const float* __restrict__ lidar_tokens,
                              const float* __restrict__ img_tokens,
                              const unsigned char* __restrict__ lmask,
                              const unsigned char* __restrict__ imask,
                              float* __restrict__ out) {
    long long gid = (long long)blockIdx.x * blockDim.x + threadIdx.x;
    int r  = (int)(gid >> 6);
    int c4 = (int)(gid & 63);
    if (r >= TOTAL) return;
    unsigned long long e = g_e1[r];
    int idx = (int)(e & 0xFFFFull);
    int b = r / NTOK;
    const float4* src;
    if (idx < NLID)
        src = (const float4*)(lidar_tokens + ((size_t)b * NLID + idx) * C);
    else
        src = (const float4*)(img_tokens + ((size_t)b * NIMG + (idx - NLID)) * C);
    ((float4*)out)[(size_t)r * 64 + c4] = src[c4];

    if (c4 == 0) {
        size_t idx_base  = (size_t)TOTAL * C;
        size_t mask_base = idx_base + TOTAL;
        out[idx_base + r] = (float)idx;
        bool m = (idx < NLID) ? (lmask[(size_t)b * NLID + idx] != 0)
                              : (imask[(size_t)b * NIMG + (idx - NLID)] != 0);
        out[mask_base + r] = m ? 1.0f : 0.0f;
    }
}

// ---------------- launch ----------------
extern "C" void kernel_launch(void* const* d_in, const int* in_sizes, int n_in,
                              void* d_out, int out_size) {
    const float* lidar_tokens = (const float*)d_in[0];
    const float* lidar_coords = (const float*)d_in[1];
    const float* img_tokens   = (const float*)d_in[2];
    const float* img_kuvd     = (const float*)d_in[3];
    const float* Km           = (const float*)d_in[4];
    const float* Tm           = (const float*)d_in[5];
    const float* Rm           = (const float*)d_in[6];
    const float* ptrans       = (const float*)d_in[7];
    const unsigned char* lm   = (const unsigned char*)d_in[8];
    const unsigned char* im   = (const unsigned char*)d_in[9];
    float* out = (float*)d_out;

    void *e0p, *e1p;
    cudaGetSymbolAddress(&e0p, g_e0);
    cudaGetSymbolAddress(&e1p, g_e1);
    unsigned long long* e0 = (unsigned long long*)e0p;
    unsigned long long* e1 = (unsigned long long*)e1p;

    setup_kernel<<<1, 32>>>(Km, Rm, out, out_size);

    dim3 gq(NTOK / 256, B);
    q_kernel<<<gq, 256>>>(lidar_coords, img_kuvd, Tm, ptrans);

    // pass 0: bits [16,24)
    key_hist_kernel<<<NBLKS, STHR>>>(lm, im);
    scan_kernel<<<B, STHR>>>();
    scatter_kernel<<<NBLKS, STHR>>>(e0, e1, 16);

    // pass 1: bits [24,32)
    hist_kernel<<<NBLKS, STHR>>>(e1, 24);
    scan_kernel<<<B, STHR>>>();
    scatter_kernel<<<NBLKS, STHR>>>(e1, e0, 24);

    // pass 2: bits [32,40)
    hist_kernel<<<NBLKS, STHR>>>(e0, 32);
    scan_kernel<<<B, STHR>>>();
    scatter_kernel<<<NBLKS, STHR>>>(e0, e1, 32);

    gather_kernel<<<(TOTAL * 64) / 256, 256>>>(lidar_tokens, img_tokens, lm, im, out);
}

// round 5
// speedup vs baseline: 2.1455x; 1.0549x over previous
#include <cuda_runtime.h>
#include <cstdint>
#include <climits>

#define B        4
#define NLID     16384
#define NIMG     4096
#define NTOK     20480
#define C        256
#define NV       6
#define TOTAL    (B*NTOK)        // 81920
#define STHR     512
#define SWARP    16
#define IPT      4
#define BLK_ITEMS (STHR*IPT)     // 2048
#define NBLK_SEG (NTOK/BLK_ITEMS)// 10
#define NBLKS    (B*NBLK_SEG)    // 40
#define CNT_SEG  (256*NBLK_SEG)  // 2560
#define CPT      (CNT_SEG/STHR)  // 5 counts per thread in inline scan

// ---------------- static device scratch (no allocations) ----------------
__device__ unsigned long long g_e0[TOTAL];
__device__ unsigned long long g_e1[TOTAL];
__device__ int4               g_q[TOTAL];
__device__ unsigned int       g_cnt0[B * CNT_SEG];
__device__ unsigned int       g_cnt1[B * CNT_SEG];
__device__ unsigned int       g_cnt2[B * CNT_SEG];
__device__ int                g_min[B][3];
__device__ int                g_max[B][3];
__device__ float              g_invK[B][NV][9];
__device__ float              g_invR[B][NV][9];

// ---------------- 3x3 inverse via adjugate in double ----------------
__device__ __forceinline__ void inv3(const float* a, float* o) {
    double m[9];
#pragma unroll
    for (int i = 0; i < 9; i++) m[i] = (double)a[i];
    double c00 =   m[4]*m[8] - m[5]*m[7];
    double c01 = -(m[3]*m[8] - m[5]*m[6]);
    double c02 =   m[3]*m[7] - m[4]*m[6];
    double det = m[0]*c00 + m[1]*c01 + m[2]*c02;
    double id  = 1.0 / det;
    o[0] = (float)( c00 * id);
    o[1] = (float)(-(m[1]*m[8] - m[2]*m[7]) * id);
    o[2] = (float)( (m[1]*m[5] - m[2]*m[4]) * id);
    o[3] = (float)( c01 * id);
    o[4] = (float)( (m[0]*m[8] - m[2]*m[6]) * id);
    o[5] = (float)(-(m[0]*m[5] - m[2]*m[3]) * id);
    o[6] = (float)( c02 * id);
    o[7] = (float)(-(m[0]*m[7] - m[1]*m[6]) * id);
    o[8] = (float)( (m[0]*m[4] - m[1]*m[3]) * id);
}

// ---------------- setup: inverses, minmax identities, zero atomic count bufs ----------------
__global__ void __launch_bounds__(1024) setup_kernel(
    const float* __restrict__ K, const float* __restrict__ R,
    float* out, int out_size) {
    int t = threadIdx.x;
    if (t < B * 3) {
        ((int*)g_min)[t] = INT_MAX;
        ((int*)g_max)[t] = INT_MIN;
    }
    if (t < B * NV) {
        int b = t / NV, v = t % NV;
        inv3(K + (size_t)t * 9, g_invK[b][v]);
        inv3(R + (size_t)t * 9, g_invR[b][v]);
    }
#pragma unroll
    for (int k = 0; k < (B * CNT_SEG) / 1024; k++) {
        g_cnt1[t + k * 1024] = 0;
        g_cnt2[t + k * 1024] = 0;
    }
    if (t == 0) {
        size_t base = (size_t)TOTAL * C + 2 * (size_t)TOTAL;
        if ((size_t)out_size >= base + 2) {
            out[base + 0] = 16384.0f;
            out[base + 1] = 1.0f;
        }
    }
}

// ---------------- quantize + per-batch min/max ----------------
__global__ void q_kernel(const float* __restrict__ lidar_coords,
                         const float* __restrict__ img_kuvd,
                         const float* __restrict__ T,
                         const float* __restrict__ post_trans) {
    int b = blockIdx.y;
    int i = blockIdx.x * blockDim.x + threadIdx.x;

    float x, y, z;
    if (i < NLID) {
        const float* c = lidar_coords + ((size_t)b * NLID + i) * 3;
        x = c[0]; y = c[1]; z = c[2];
    } else {
        int j = i - NLID;
        const float* kv = img_kuvd + ((size_t)b * NIMG + j) * 4;
        int cam = (int)kv[0];
        float u = kv[1], v = kv[2], D = kv[3];
        const float* tt = post_trans + (b * NV + cam) * 3;
        float u1 = u - tt[0], v1 = v - tt[1], w1 = 1.0f - tt[2];
        const float* iR = g_invR[b][cam];
        float rx = fmaf(iR[0], u1, fmaf(iR[1], v1, iR[2] * w1));
        float ry = fmaf(iR[3], u1, fmaf(iR[4], v1, iR[5] * w1));
        const float* iK = g_invK[b][cam];
        float cx = fmaf(iK[0], rx, fmaf(iK[1], ry, iK[2])) * D;
        float cy = fmaf(iK[3], rx, fmaf(iK[4], ry, iK[5])) * D;
        float cz = fmaf(iK[6], rx, fmaf(iK[7], ry, iK[8])) * D;
        const float* Tm = T + (size_t)(b * NV + cam) * 16;
        x = fmaf(Tm[0], cx, fmaf(Tm[1], cy, fmaf(Tm[2],  cz, Tm[3])));
        y = fmaf(Tm[4], cx, fmaf(Tm[5], cy, fmaf(Tm[6],  cz, Tm[7])));
        z = fmaf(Tm[8], cx, fmaf(Tm[9], cy, fmaf(Tm[10], cz, Tm[11])));
    }
    int q0 = (int)floorf(x), q1 = (int)floorf(y), q2 = (int)floorf(z);
    g_q[b * NTOK + i] = make_int4(q0, q1, q2, 0);

    __shared__ int smin[3], smax[3];
    if (threadIdx.x < 3) { smin[threadIdx.x] = INT_MAX; smax[threadIdx.x] = INT_MIN; }
    __syncthreads();
    atomicMin(&smin[0], q0); atomicMax(&smax[0], q0);
    atomicMin(&smin[1], q1); atomicMax(&smax[1], q1);
    atomicMin(&smin[2], q2); atomicMax(&smax[2], q2);
    __syncthreads();
    if (threadIdx.x < 3) {
        atomicMin(&g_min[b][threadIdx.x], smin[threadIdx.x]);
        atomicMax(&g_max[b][threadIdx.x], smax[threadIdx.x]);
    }
}

// ---------------- build keys + pass-0 per-block histogram ----------------
__global__ void key_hist_kernel(const unsigned char* __restrict__ lmask,
                                const unsigned char* __restrict__ imask) {
    __shared__ unsigned hist[256];
    int tid = threadIdx.x;
    if (tid < 256) hist[tid] = 0;
    __syncthreads();

    int blk = blockIdx.x, seg = blk / NBLK_SEG, bib = blk % NBLK_SEG;
    int base = seg * NTOK + bib * BLK_ITEMS;
    int m0 = g_min[seg][0], m1 = g_min[seg][1], m2 = g_min[seg][2];
    int M1 = g_max[seg][1] - m1, M2 = g_max[seg][2] - m2;

#pragma unroll
    for (int k = 0; k < IPT; k++) {
        int gid = base + tid + k * STHR;
        int i = gid - seg * NTOK;
        int4 q = g_q[gid];
        int d0 = q.x - m0, d1 = q.y - m1, d2 = q.z - m2;
        int s1 = (d0 & 1)        ? (M1 - d1) : d1;
        int s2 = ((d0 + d1) & 1) ? (M2 - d2) : d2;
        bool msk = (i < NLID) ? (lmask[(size_t)seg * NLID + i] != 0)
                              : (imask[(size_t)seg * NIMG + (i - NLID)] != 0);
        unsigned key = msk ? 0xFFFFFFu
                           : (((unsigned)d0 << 16) | ((unsigned)s1 << 8) | (unsigned)s2);
        g_e0[gid] = ((unsigned long long)key << 16) | (unsigned)i;
        atomicAdd(&hist[key & 255u], 1u);
    }
    __syncthreads();
    if (tid < 256)
        g_cnt0[seg * CNT_SEG + tid * NBLK_SEG + bib] = hist[tid];
}

// ---------------- fused scatter: inline segment scan + stable scatter + next-pass hist ----------------
template <bool DO_NEXT>
__global__ void __launch_bounds__(STHR) scatter_kernel(
    const unsigned long long* __restrict__ src,
    unsigned long long* __restrict__ dst,
    const unsigned* __restrict__ cnt_cur,
    unsigned* __restrict__ cnt_next,
    int shift, int shift_next)
{
    __shared__ unsigned sbase[256];
    __shared__ unsigned whist[SWARP][256];
    __shared__ unsigned wsum[SWARP];
    int tid = threadIdx.x;
    int lane = tid & 31, w = tid >> 5;
    int blk = blockIdx.x, seg = blk / NBLK_SEG, bib = blk % NBLK_SEG;
    const unsigned* cnt = cnt_cur + seg * CNT_SEG;

    // zero per-warp hist
#pragma unroll
    for (int k = 0; k < (SWARP * 256) / STHR; k++)
        ((unsigned*)whist)[tid + k * STHR] = 0;

    // ---- inline exclusive scan of 2560 counts (digit-major, block) ----
    unsigned v[CPT];
#pragma unroll
    for (int k = 0; k < CPT; k++) v[k] = cnt[tid * CPT + k];
    unsigned sum = 0;
#pragma unroll
    for (int k = 0; k < CPT; k++) { unsigned t = v[k]; v[k] = sum; sum += t; }
    unsigned s = sum;
#pragma unroll
    for (int off = 1; off < 32; off <<= 1) {
        unsigned n = __shfl_up_sync(0xFFFFFFFFu, s, off);
        if (lane >= off) s += n;
    }
    if (lane == 31) wsum[w] = s;
    __syncthreads();
    if (tid == 0) {
        unsigned run = 0;
#pragma unroll
        for (int i = 0; i < SWARP; i++) { unsigned t = wsum[i]; wsum[i] = run; run += t; }
    }
    __syncthreads();
    unsigned ex = wsum[w] + (s - sum);
#pragma unroll
    for (int k = 0; k < CPT; k++) {
        unsigned j = tid * CPT + k;              // j = digit*NBLK_SEG + block
        if ((int)(j % NBLK_SEG) == bib) sbase[j / NBLK_SEG] = ex + v[k];
    }

    // ---- ranking: stable per-warp order via match_any ----
    const unsigned long long* sp = src + seg * NTOK + bib * BLK_ITEMS;
    unsigned long long e[IPT];
    unsigned dg[IPT], rk[IPT];
#pragma unroll
    for (int it = 0; it < IPT; it++) {
        int i = w * (IPT * 32) + it * 32 + lane;
        e[it]  = sp[i];
        dg[it] = (unsigned)(e[it] >> shift) & 255u;
        unsigned mset = __match_any_sync(0xFFFFFFFFu, dg[it]);
        unsigned before = whist[w][dg[it]];
        rk[it] = before + __popc(mset & ((1u << lane) - 1u));
        __syncwarp();
        if ((mset & (0u - mset)) == (1u << lane))
            whist[w][dg[it]] = before + __popc(mset);
        __syncwarp();
    }
    __syncthreads();

    // ---- per-digit exclusive over warps ----
    if (tid < 256) {
        unsigned run = 0;
#pragma unroll
        for (int ww = 0; ww < SWARP; ww++) {
            unsigned t = whist[ww][tid];
            whist[ww][tid] = run;
            run += t;
        }
    }
    __syncthreads();

    // ---- scatter + fused next-pass histogram ----
    unsigned long long* d = dst + seg * NTOK;
    unsigned* cn = DO_NEXT ? (cnt_next + seg * CNT_SEG) : nullptr;
#pragma unroll
    for (int it = 0; it < IPT; it++) {
        unsigned pos = sbase[dg[it]] + whist[w][dg[it]] + rk[it];
        d[pos] = e[it];
        if (DO_NEXT) {
            unsigned d2 = (unsigned)(e[it] >> shift_next) & 255u;
            atomicAdd(&cn[d2 * NBLK_SEG + (pos >> 11)], 1u);
        }
    }
}

// ---------------- gather rows + idx/mask outputs ----------------
__global__ void gather_kernel(const float* __restrict__ lidar_tokens,
                              const float* __restrict__ img_tokens,
                              const unsigned char* __restrict__ lmask,
                              const unsigned char* __restrict__ imask,
                              float* __restrict__ out) {
    long long gid = (long long)blockIdx.x * blockDim.x + threadIdx.x;
    int r  = (int)(gid >> 6);
    int c4 = (int)(gid & 63);
    if (r >= TOTAL) return;
    unsigned long long e = g_e1[r];
    int idx = (int)(e & 0xFFFFull);
    int b = r / NTOK;
    const float4* src;
    if (idx < NLID)
        src = (const float4*)(lidar_tokens + ((size_t)b * NLID + idx) * C);
    else
        src = (const float4*)(img_tokens + ((size_t)b * NIMG + (idx - NLID)) * C);
    ((float4*)out)[(size_t)r * 64 + c4] = src[c4];

    if (c4 == 0) {
        size_t idx_base  = (size_t)TOTAL * C;
        size_t mask_base = idx_base + TOTAL;
        out[idx_base + r] = (float)idx;
        bool m = (idx < NLID) ? (lmask[(size_t)b * NLID + idx] != 0)
                              : (imask[(size_t)b * NIMG + (idx - NLID)] != 0);
        out[mask_base + r] = m ? 1.0f : 0.0f;
    }
}

// ---------------- launch ----------------
extern "C" void kernel_launch(void* const* d_in, const int* in_sizes, int n_in,
                              void* d_out, int out_size) {
    const float* lidar_tokens = (const float*)d_in[0];
    const float* lidar_coords = (const float*)d_in[1];
    const float* img_tokens   = (const float*)d_in[2];
    const float* img_kuvd     = (const float*)d_in[3];
    const float* Km           = (const float*)d_in[4];
    const float* Tm           = (const float*)d_in[5];
    const float* Rm           = (const float*)d_in[6];
    const float* ptrans       = (const float*)d_in[7];
    const unsigned char* lm   = (const unsigned char*)d_in[8];
    const unsigned char* im   = (const unsigned char*)d_in[9];
    float* out = (float*)d_out;

    void *e0p, *e1p, *c0p, *c1p, *c2p;
    cudaGetSymbolAddress(&e0p, g_e0);
    cudaGetSymbolAddress(&e1p, g_e1);
    cudaGetSymbolAddress(&c0p, g_cnt0);
    cudaGetSymbolAddress(&c1p, g_cnt1);
    cudaGetSymbolAddress(&c2p, g_cnt2);
    unsigned long long* e0 = (unsigned long long*)e0p;
    unsigned long long* e1 = (unsigned long long*)e1p;
    unsigned* c0 = (unsigned*)c0p;
    unsigned* c1 = (unsigned*)c1p;
    unsigned* c2 = (unsigned*)c2p;

    setup_kernel<<<1, 1024>>>(Km, Rm, out, out_size);

    dim3 gq(NTOK / 256, B);
    q_kernel<<<gq, 256>>>(lidar_coords, img_kuvd, Tm, ptrans);

    key_hist_kernel<<<NBLKS, STHR>>>(lm, im);

    scatter_kernel<true ><<<NBLKS, STHR>>>(e0, e1, c0, c1, 16, 24);
    scatter_kernel<true ><<<NBLKS, STHR>>>(e1, e0, c1, c2, 24, 32);
    scatter_kernel<false><<<NBLKS, STHR>>>(e0, e1, c2, nullptr, 32, 0);

    gather_kernel<<<(TOTAL * 64) / 256, 256>>>(lidar_tokens, img_tokens, lm, im, out);
}

// round 6
// speedup vs baseline: 2.2549x; 1.0510x over previous
#include <cuda_runtime.h>
#include <cstdint>
#include <climits>

#define B        4
#define NLID     16384
#define NIMG     4096
#define NTOK     20480
#define C        256
#define NV       6
#define TOTAL    (B*NTOK)        // 81920
#define STHR     256
#define SWARP    8
#define IPT      4
#define BLK_ITEMS (STHR*IPT)     // 1024
#define NBLK_SEG (NTOK/BLK_ITEMS)// 20
#define NBLKS    (B*NBLK_SEG)    // 80
#define CNT_SEG  (256*NBLK_SEG)  // 5120
#define CPT      (CNT_SEG/STHR)  // 20  (== NBLK_SEG)

// ---------------- static device scratch (no allocations) ----------------
__device__ unsigned long long g_e0[TOTAL];
__device__ unsigned long long g_e1[TOTAL];
__device__ int4               g_q[TOTAL];
__device__ unsigned int       g_cnt0[B * CNT_SEG];
__device__ unsigned int       g_cnt1[B * CNT_SEG];
__device__ unsigned int       g_cnt2[B * CNT_SEG];
__device__ int                g_min[B][3];
__device__ int                g_max[B][3];
__device__ float              g_invK[B][NV][9];
__device__ float              g_invR[B][NV][9];

// ---------------- 3x3 inverse via adjugate in double ----------------
__device__ __forceinline__ void inv3(const float* a, float* o) {
    double m[9];
#pragma unroll
    for (int i = 0; i < 9; i++) m[i] = (double)a[i];
    double c00 =   m[4]*m[8] - m[5]*m[7];
    double c01 = -(m[3]*m[8] - m[5]*m[6]);
    double c02 =   m[3]*m[7] - m[4]*m[6];
    double det = m[0]*c00 + m[1]*c01 + m[2]*c02;
    double id  = 1.0 / det;
    o[0] = (float)( c00 * id);
    o[1] = (float)(-(m[1]*m[8] - m[2]*m[7]) * id);
    o[2] = (float)( (m[1]*m[5] - m[2]*m[4]) * id);
    o[3] = (float)( c01 * id);
    o[4] = (float)( (m[0]*m[8] - m[2]*m[6]) * id);
    o[5] = (float)(-(m[0]*m[5] - m[2]*m[3]) * id);
    o[6] = (float)( c02 * id);
    o[7] = (float)(-(m[0]*m[7] - m[1]*m[6]) * id);
    o[8] = (float)( (m[0]*m[4] - m[1]*m[3]) * id);
}

// ---------------- setup ----------------
__global__ void __launch_bounds__(1024) setup_kernel(
    const float* __restrict__ K, const float* __restrict__ R,
    float* out, int out_size) {
    int t = threadIdx.x;
    if (t < B * 3) {
        ((int*)g_min)[t] = INT_MAX;
        ((int*)g_max)[t] = INT_MIN;
    }
    if (t < B * NV) {
        int b = t / NV, v = t % NV;
        inv3(K + (size_t)t * 9, g_invK[b][v]);
        inv3(R + (size_t)t * 9, g_invR[b][v]);
    }
#pragma unroll
    for (int k = 0; k < (B * CNT_SEG) / 1024; k++) {
        g_cnt1[t + k * 1024] = 0;
        g_cnt2[t + k * 1024] = 0;
    }
    if (t == 0) {
        size_t base = (size_t)TOTAL * C + 2 * (size_t)TOTAL;
        if ((size_t)out_size >= base + 2) {
            out[base + 0] = 16384.0f;
            out[base + 1] = 1.0f;
        }
    }
}

// ---------------- quantize + per-batch min/max ----------------
__global__ void q_kernel(const float* __restrict__ lidar_coords,
                         const float* __restrict__ img_kuvd,
                         const float* __restrict__ T,
                         const float* __restrict__ post_trans) {
    int b = blockIdx.y;
    int i = blockIdx.x * blockDim.x + threadIdx.x;

    float x, y, z;
    if (i < NLID) {
        const float* c = lidar_coords + ((size_t)b * NLID + i) * 3;
        x = c[0]; y = c[1]; z = c[2];
    } else {
        int j = i - NLID;
        const float* kv = img_kuvd + ((size_t)b * NIMG + j) * 4;
        int cam = (int)kv[0];
        float u = kv[1], v = kv[2], D = kv[3];
        const float* tt = post_trans + (b * NV + cam) * 3;
        float u1 = u - tt[0], v1 = v - tt[1], w1 = 1.0f - tt[2];
        const float* iR = g_invR[b][cam];
        float rx = fmaf(iR[0], u1, fmaf(iR[1], v1, iR[2] * w1));
        float ry = fmaf(iR[3], u1, fmaf(iR[4], v1, iR[5] * w1));
        const float* iK = g_invK[b][cam];
        float cx = fmaf(iK[0], rx, fmaf(iK[1], ry, iK[2])) * D;
        float cy = fmaf(iK[3], rx, fmaf(iK[4], ry, iK[5])) * D;
        float cz = fmaf(iK[6], rx, fmaf(iK[7], ry, iK[8])) * D;
        const float* Tm = T + (size_t)(b * NV + cam) * 16;
        x = fmaf(Tm[0], cx, fmaf(Tm[1], cy, fmaf(Tm[2],  cz, Tm[3])));
        y = fmaf(Tm[4], cx, fmaf(Tm[5], cy, fmaf(Tm[6],  cz, Tm[7])));
        z = fmaf(Tm[8], cx, fmaf(Tm[9], cy, fmaf(Tm[10], cz, Tm[11])));
    }
    int q0 = (int)floorf(x), q1 = (int)floorf(y), q2 = (int)floorf(z);
    g_q[b * NTOK + i] = make_int4(q0, q1, q2, 0);

    __shared__ int smin[3], smax[3];
    if (threadIdx.x < 3) { smin[threadIdx.x] = INT_MAX; smax[threadIdx.x] = INT_MIN; }
    __syncthreads();
    atomicMin(&smin[0], q0); atomicMax(&smax[0], q0);
    atomicMin(&smin[1], q1); atomicMax(&smax[1], q1);
    atomicMin(&smin[2], q2); atomicMax(&smax[2], q2);
    __syncthreads();
    if (threadIdx.x < 3) {
        atomicMin(&g_min[b][threadIdx.x], smin[threadIdx.x]);
        atomicMax(&g_max[b][threadIdx.x], smax[threadIdx.x]);
    }
}

// ---------------- build keys + pass-0 per-block histogram ----------------
__global__ void __launch_bounds__(STHR) key_hist_kernel(
    const unsigned char* __restrict__ lmask,
    const unsigned char* __restrict__ imask) {
    __shared__ unsigned hist[256];
    int tid = threadIdx.x;
    hist[tid] = 0;
    __syncthreads();

    int blk = blockIdx.x, seg = blk / NBLK_SEG, bib = blk % NBLK_SEG;
    int base = seg * NTOK + bib * BLK_ITEMS;
    int m0 = g_min[seg][0], m1 = g_min[seg][1], m2 = g_min[seg][2];
    int M1 = g_max[seg][1] - m1, M2 = g_max[seg][2] - m2;

#pragma unroll
    for (int k = 0; k < IPT; k++) {
        int gid = base + tid + k * STHR;
        int i = gid - seg * NTOK;
        int4 q = g_q[gid];
        int d0 = q.x - m0, d1 = q.y - m1, d2 = q.z - m2;
        int s1 = (d0 & 1)        ? (M1 - d1) : d1;
        int s2 = ((d0 + d1) & 1) ? (M2 - d2) : d2;
        bool msk = (i < NLID) ? (lmask[(size_t)seg * NLID + i] != 0)
                              : (imask[(size_t)seg * NIMG + (i - NLID)] != 0);
        unsigned key = msk ? 0xFFFFFFu
                           : (((unsigned)d0 << 16) | ((unsigned)s1 << 8) | (unsigned)s2);
        g_e0[gid] = ((unsigned long long)key << 16) | (unsigned)i;
        atomicAdd(&hist[key & 255u], 1u);
    }
    __syncthreads();
    g_cnt0[seg * CNT_SEG + tid * NBLK_SEG + bib] = hist[tid];
}

// ---------------- fused scatter: inline scan + stable scatter + next-pass hist ----------------
template <bool DO_NEXT>
__global__ void __launch_bounds__(STHR) scatter_kernel(
    const unsigned long long* __restrict__ src,
    unsigned long long* __restrict__ dst,
    const unsigned* __restrict__ cnt_cur,
    unsigned* __restrict__ cnt_next,
    int shift, int shift_next)
{
    __shared__ unsigned sbase[256];
    __shared__ unsigned whist[SWARP][256];
    __shared__ unsigned wsum[SWARP];
    int tid = threadIdx.x;
    int lane = tid & 31, w = tid >> 5;
    int blk = blockIdx.x, seg = blk / NBLK_SEG, bib = blk % NBLK_SEG;
    const unsigned* cnt = cnt_cur + seg * CNT_SEG;

    // zero per-warp hist
#pragma unroll
    for (int k = 0; k < (SWARP * 256) / STHR; k++)
        ((unsigned*)whist)[tid + k * STHR] = 0;

    // ---- inline exclusive scan: thread tid owns digit tid (20 block counts) ----
    unsigned v[CPT];
#pragma unroll
    for (int k = 0; k < CPT; k++) v[k] = cnt[tid * CPT + k];
    unsigned sum = 0;
#pragma unroll
    for (int k = 0; k < CPT; k++) { unsigned t = v[k]; v[k] = sum; sum += t; }
    unsigned s = sum;
#pragma unroll
    for (int off = 1; off < 32; off <<= 1) {
        unsigned n = __shfl_up_sync(0xFFFFFFFFu, s, off);
        if (lane >= off) s += n;
    }
    if (lane == 31) wsum[w] = s;
    __syncthreads();
    if (tid == 0) {
        unsigned run = 0;
#pragma unroll
        for (int i = 0; i < SWARP; i++) { unsigned t = wsum[i]; wsum[i] = run; run += t; }
    }
    __syncthreads();
    sbase[tid] = wsum[w] + (s - sum) + v[bib];   // digit == tid

    // ---- ranking: stable per-warp order via match_any ----
    const unsigned long long* sp = src + seg * NTOK + bib * BLK_ITEMS;
    unsigned long long e[IPT];
    unsigned dg[IPT], rk[IPT];
#pragma unroll
    for (int it = 0; it < IPT; it++) {
        int i = w * (IPT * 32) + it * 32 + lane;
        e[it]  = sp[i];
        dg[it] = (unsigned)(e[it] >> shift) & 255u;
        unsigned mset = __match_any_sync(0xFFFFFFFFu, dg[it]);
        unsigned before = whist[w][dg[it]];
        rk[it] = before + __popc(mset & ((1u << lane) - 1u));
        __syncwarp();
        if ((mset & (0u - mset)) == (1u << lane))
            whist[w][dg[it]] = before + __popc(mset);
        __syncwarp();
    }
    __syncthreads();

    // ---- per-digit exclusive over warps (digit == tid) ----
    {
        unsigned run = 0;
#pragma unroll
        for (int ww = 0; ww < SWARP; ww++) {
            unsigned t = whist[ww][tid];
            whist[ww][tid] = run;
            run += t;
        }
    }
    __syncthreads();

    // ---- scatter + fused next-pass histogram ----
    unsigned long long* d = dst + seg * NTOK;
    unsigned* cn = DO_NEXT ? (cnt_next + seg * CNT_SEG) : nullptr;
#pragma unroll
    for (int it = 0; it < IPT; it++) {
        unsigned pos = sbase[dg[it]] + whist[w][dg[it]] + rk[it];
        d[pos] = e[it];
        if (DO_NEXT) {
            unsigned d2 = (unsigned)(e[it] >> shift_next) & 255u;
            atomicAdd(&cn[d2 * NBLK_SEG + (pos >> 10)], 1u);
        }
    }
}

// ---------------- gather rows + idx/mask outputs ----------------
__global__ void gather_kernel(const float* __restrict__ lidar_tokens,
                              const float* __restrict__ img_tokens,
                              const unsigned char* __restrict__ lmask,
                              const unsigned char* __restrict__ imask,
                              float* __restrict__ out) {
    long long gid = (long long)blockIdx.x * blockDim.x + threadIdx.x;
    int r  = (int)(gid >> 6);
    int c4 = (int)(gid & 63);
    if (r >= TOTAL) return;
    unsigned long long e = g_e1[r];
    int idx = (int)(e & 0xFFFFull);
    int b = r / NTOK;
    const float4* src;
    if (idx < NLID)
        src = (const float4*)(lidar_tokens + ((size_t)b * NLID + idx) * C);
    else
        src = (const float4*)(img_tokens + ((size_t)b * NIMG + (idx - NLID)) * C);
    ((float4*)out)[(size_t)r * 64 + c4] = src[c4];

    if (c4 == 0) {
        size_t idx_base  = (size_t)TOTAL * C;
        size_t mask_base = idx_base + TOTAL;
        out[idx_base + r] = (float)idx;
        bool m = (idx < NLID) ? (lmask[(size_t)b * NLID + idx] != 0)
                              : (imask[(size_t)b * NIMG + (idx - NLID)] != 0);
        out[mask_base + r] = m ? 1.0f : 0.0f;
    }
}

// ---------------- launch ----------------
extern "C" void kernel_launch(void* const* d_in, const int* in_sizes, int n_in,
                              void* d_out, int out_size) {
    const float* lidar_tokens = (const float*)d_in[0];
    const float* lidar_coords = (const float*)d_in[1];
    const float* img_tokens   = (const float*)d_in[2];
    const float* img_kuvd     = (const float*)d_in[3];
    const float* Km           = (const float*)d_in[4];
    const float* Tm           = (const float*)d_in[5];
    const float* Rm           = (const float*)d_in[6];
    const float* ptrans       = (const float*)d_in[7];
    const unsigned char* lm   = (const unsigned char*)d_in[8];
    const unsigned char* im   = (const unsigned char*)d_in[9];
    float* out = (float*)d_out;

    void *e0p, *e1p, *c0p, *c1p, *c2p;
    cudaGetSymbolAddress(&e0p, g_e0);
    cudaGetSymbolAddress(&e1p, g_e1);
    cudaGetSymbolAddress(&c0p, g_cnt0);
    cudaGetSymbolAddress(&c1p, g_cnt1);
    cudaGetSymbolAddress(&c2p, g_cnt2);
    unsigned long long* e0 = (unsigned long long*)e0p;
    unsigned long long* e1 = (unsigned long long*)e1p;
    unsigned* c0 = (unsigned*)c0p;
    unsigned* c1 = (unsigned*)c1p;
    unsigned* c2 = (unsigned*)c2p;

    setup_kernel<<<1, 1024>>>(Km, Rm, out, out_size);

    dim3 gq(NTOK / 256, B);
    q_kernel<<<gq, 256>>>(lidar_coords, img_kuvd, Tm, ptrans);

    key_hist_kernel<<<NBLKS, STHR>>>(lm, im);

    scatter_kernel<true ><<<NBLKS, STHR>>>(e0, e1, c0, c1, 16, 24);
    scatter_kernel<true ><<<NBLKS, STHR>>>(e1, e0, c1, c2, 24, 32);
    scatter_kernel<false><<<NBLKS, STHR>>>(e0, e1, c2, nullptr, 32, 0);

    gather_kernel<<<(TOTAL * 64) / 256, 256>>>(lidar_tokens, img_tokens, lm, im, out);
}

// round 7
// speedup vs baseline: 2.4896x; 1.1041x over previous
#include <cuda_runtime.h>
#include <cstdint>
#include <climits>

#define B        4
#define NLID     16384
#define NIMG     4096
#define NTOK     20480
#define C        256
#define NV       6
#define TOTAL    (B*NTOK)        // 81920
#define STHR     256
#define SWARP    8
#define IPT      4
#define BLK_ITEMS 1024
#define NBLK_SEG 20              // blocks per segment
#define NBLKS    80
#define CNT_SEG  (256*NBLK_SEG)  // 5120
#define CPT      20              // counts per thread in inline scan (== NBLK_SEG)

// ---------------- static device scratch (no allocations) ----------------
__device__ unsigned long long g_e0[TOTAL];
__device__ unsigned long long g_e1[TOTAL];
__device__ unsigned int       g_cnt0[B * CNT_SEG];
__device__ unsigned int       g_cnt1[B * CNT_SEG];
__device__ unsigned int       g_cnt2[B * CNT_SEG];
__device__ int                g_bmin[B][NBLK_SEG][3];
__device__ int                g_bmax[B][NBLK_SEG][3];
__device__ unsigned int       g_ctr;    // monotonic arrival counter
__device__ unsigned int       g_base;   // per-launch base (updated at end of launch)

// ---------------- 3x3 inverse via adjugate in double ----------------
__device__ __forceinline__ void inv3(const float* a, float* o) {
    double m[9];
#pragma unroll
    for (int i = 0; i < 9; i++) m[i] = (double)a[i];
    double c00 =   m[4]*m[8] - m[5]*m[7];
    double c01 = -(m[3]*m[8] - m[5]*m[6]);
    double c02 =   m[3]*m[7] - m[4]*m[6];
    double det = m[0]*c00 + m[1]*c01 + m[2]*c02;
    double id  = 1.0 / det;
    o[0] = (float)( c00 * id);
    o[1] = (float)(-(m[1]*m[8] - m[2]*m[7]) * id);
    o[2] = (float)( (m[1]*m[5] - m[2]*m[4]) * id);
    o[3] = (float)( c01 * id);
    o[4] = (float)( (m[0]*m[8] - m[2]*m[6]) * id);
    o[5] = (float)(-(m[0]*m[5] - m[2]*m[3]) * id);
    o[6] = (float)( c02 * id);
    o[7] = (float)(-(m[0]*m[7] - m[1]*m[6]) * id);
    o[8] = (float)( (m[0]*m[4] - m[1]*m[3]) * id);
}

// ---------------- manual grid barrier (all NBLKS blocks co-resident) ----------------
__device__ __forceinline__ void grid_barrier(unsigned base, unsigned idx) {
    __syncthreads();
    if (threadIdx.x == 0) {
        __threadfence();                       // release this block's writes
        atomicAdd(&g_ctr, 1u);
        unsigned target = idx * NBLKS;
        while ((*(volatile unsigned*)&g_ctr) - base < target) { }
        __threadfence();
    }
    __syncthreads();
}

// ---------------- one stable radix pass: inline scan + rank + scatter + next hist ----------------
__device__ __forceinline__ void pass_body(
    const unsigned long long e[IPT],
    const unsigned* __restrict__ cnt_seg,        // current pass counts (this segment)
    unsigned long long* __restrict__ dst_seg,    // destination (this segment)
    unsigned* __restrict__ cnt_next_seg,         // next pass counts or nullptr
    int shift, int shift_next,
    int bib, int w, int lane, int tid,
    unsigned* sbase, unsigned (*whist)[256], unsigned* wsum)
{
    // zero per-warp hist (thread tid owns column tid of all 8 rows)
#pragma unroll
    for (int k = 0; k < SWARP; k++) whist[k][tid] = 0;

    // ---- inline exclusive scan: thread tid owns digit tid (20 block counts) ----
    unsigned v[CPT];
#pragma unroll
    for (int k = 0; k < CPT; k++) v[k] = __ldcg(&cnt_seg[tid * CPT + k]);
    unsigned sum = 0;
#pragma unroll
    for (int k = 0; k < CPT; k++) { unsigned t = v[k]; v[k] = sum; sum += t; }
    unsigned s = sum;
#pragma unroll
    for (int off = 1; off < 32; off <<= 1) {
        unsigned n = __shfl_up_sync(0xFFFFFFFFu, s, off);
        if (lane >= off) s += n;
    }
    if (lane == 31) wsum[w] = s;
    __syncthreads();
    if (tid == 0) {
        unsigned run = 0;
#pragma unroll
        for (int i = 0; i < SWARP; i++) { unsigned t = wsum[i]; wsum[i] = run; run += t; }
    }
    __syncthreads();
    sbase[tid] = wsum[w] + (s - sum) + v[bib];   // digit == tid

    // ---- ranking: stable per-warp order via match_any ----
    unsigned dg[IPT], rk[IPT];
#pragma unroll
    for (int it = 0; it < IPT; it++) {
        dg[it] = (unsigned)(e[it] >> shift) & 255u;
        unsigned mset = __match_any_sync(0xFFFFFFFFu, dg[it]);
        unsigned before = whist[w][dg[it]];
        rk[it] = before + __popc(mset & ((1u << lane) - 1u));
        __syncwarp();
        if ((mset & (0u - mset)) == (1u << lane))
            whist[w][dg[it]] = before + __popc(mset);
        __syncwarp();
    }
    __syncthreads();

    // ---- per-digit exclusive over warps (digit == tid) ----
    {
        unsigned run = 0;
#pragma unroll
        for (int ww = 0; ww < SWARP; ww++) {
            unsigned t = whist[ww][tid];
            whist[ww][tid] = run;
            run += t;
        }
    }
    __syncthreads();

    // ---- scatter + fused next-pass histogram ----
#pragma unroll
    for (int it = 0; it < IPT; it++) {
        unsigned pos = sbase[dg[it]] + whist[w][dg[it]] + rk[it];
        dst_seg[pos] = e[it];
        if (cnt_next_seg) {
            unsigned d2 = (unsigned)(e[it] >> shift_next) & 255u;
            atomicAdd(&cnt_next_seg[d2 * NBLK_SEG + (pos >> 10)], 1u);
        }
    }
}

// ---------------- mega kernel: geometry + keys + full 3-pass sort ----------------
__global__ void __launch_bounds__(STHR, 1) mega_kernel(
    const float* __restrict__ lidar_coords,
    const float* __restrict__ img_kuvd,
    const float* __restrict__ Kmat,
    const float* __restrict__ Tmat,
    const float* __restrict__ Rmat,
    const float* __restrict__ ptrans,
    const unsigned char* __restrict__ lmask,
    const unsigned char* __restrict__ imask)
{
    __shared__ float    sInvK[NV * 9], sInvR[NV * 9];
    __shared__ int      smin[3], smax[3];
    __shared__ unsigned sbase[256];
    __shared__ unsigned whist[SWARP][256];
    __shared__ unsigned wsum[SWARP];
    __shared__ unsigned hist[256];

    int tid = threadIdx.x, lane = tid & 31, w = tid >> 5;
    int blk = blockIdx.x, seg = blk / NBLK_SEG, bib = blk % NBLK_SEG;
    unsigned base = g_base;                // stable per launch

    if (tid < 3) { smin[tid] = INT_MAX; smax[tid] = INT_MIN; }
    if (tid < NV)
        inv3(Kmat + ((size_t)seg * NV + tid) * 9, sInvK + tid * 9);
    else if (tid < 2 * NV)
        inv3(Rmat + ((size_t)seg * NV + (tid - NV)) * 9, sInvR + (tid - NV) * 9);
    // zero next-pass counters: 80 blocks x 256 thr == B*CNT_SEG entries exactly
    g_cnt1[blk * STHR + tid] = 0;
    g_cnt2[blk * STHR + tid] = 0;
    __syncthreads();

    // ---- Phase A: quantize own 1024 items (registers) + block min/max ----
    int q0r[IPT], q1r[IPT], q2r[IPT];
    int mn0 = INT_MAX, mn1 = INT_MAX, mn2 = INT_MAX;
    int mx0 = INT_MIN, mx1 = INT_MIN, mx2 = INT_MIN;
#pragma unroll
    for (int it = 0; it < IPT; it++) {
        int i = bib * BLK_ITEMS + w * (IPT * 32) + it * 32 + lane;
        float x, y, z;
        if (i < NLID) {
            const float* c = lidar_coords + ((size_t)seg * NLID + i) * 3;
            x = c[0]; y = c[1]; z = c[2];
        } else {
            int j = i - NLID;
            const float* kv = img_kuvd + ((size_t)seg * NIMG + j) * 4;
            int cam = (int)kv[0];
            float u = kv[1], v = kv[2], D = kv[3];
            const float* tt = ptrans + (seg * NV + cam) * 3;
            float u1 = u - tt[0], v1 = v - tt[1], w1 = 1.0f - tt[2];
            const float* iR = sInvR + cam * 9;
            float rx = fmaf(iR[0], u1, fmaf(iR[1], v1, iR[2] * w1));
            float ry = fmaf(iR[3], u1, fmaf(iR[4], v1, iR[5] * w1));
            const float* iK = sInvK + cam * 9;
            float cx = fmaf(iK[0], rx, fmaf(iK[1], ry, iK[2])) * D;
            float cy = fmaf(iK[3], rx, fmaf(iK[4], ry, iK[5])) * D;
            float cz = fmaf(iK[6], rx, fmaf(iK[7], ry, iK[8])) * D;
            const float* Tm = Tmat + (size_t)(seg * NV + cam) * 16;
            x = fmaf(Tm[0], cx, fmaf(Tm[1], cy, fmaf(Tm[2],  cz, Tm[3])));
            y = fmaf(Tm[4], cx, fmaf(Tm[5], cy, fmaf(Tm[6],  cz, Tm[7])));
            z = fmaf(Tm[8], cx, fmaf(Tm[9], cy, fmaf(Tm[10], cz, Tm[11])));
        }
        int q0 = (int)floorf(x), q1 = (int)floorf(y), q2 = (int)floorf(z);
        q0r[it] = q0; q1r[it] = q1; q2r[it] = q2;
        mn0 = min(mn0, q0); mx0 = max(mx0, q0);
        mn1 = min(mn1, q1); mx1 = max(mx1, q1);
        mn2 = min(mn2, q2); mx2 = max(mx2, q2);
    }
#pragma unroll
    for (int off = 16; off; off >>= 1) {
        mn0 = min(mn0, __shfl_xor_sync(0xFFFFFFFFu, mn0, off));
        mn1 = min(mn1, __shfl_xor_sync(0xFFFFFFFFu, mn1, off));
        mn2 = min(mn2, __shfl_xor_sync(0xFFFFFFFFu, mn2, off));
        mx0 = max(mx0, __shfl_xor_sync(0xFFFFFFFFu, mx0, off));
        mx1 = max(mx1, __shfl_xor_sync(0xFFFFFFFFu, mx1, off));
        mx2 = max(mx2, __shfl_xor_sync(0xFFFFFFFFu, mx2, off));
    }
    if (lane == 0) {
        atomicMin(&smin[0], mn0); atomicMax(&smax[0], mx0);
        atomicMin(&smin[1], mn1); atomicMax(&smax[1], mx1);
        atomicMin(&smin[2], mn2); atomicMax(&smax[2], mx2);
    }
    __syncthreads();
    if (tid < 3) {
        g_bmin[seg][bib][tid] = smin[tid];
        g_bmax[seg][bib][tid] = smax[tid];
    }

    grid_barrier(base, 1);

    // ---- Phase B: segment min/max + keys (registers) + pass-0 histogram ----
    hist[tid] = 0;
    if (w < 6) {
        int d = w % 3;
        bool ismax = (w >= 3);
        int val = ismax ? INT_MIN : INT_MAX;
        if (lane < NBLK_SEG)
            val = ismax ? __ldcg(&g_bmax[seg][lane][d]) : __ldcg(&g_bmin[seg][lane][d]);
#pragma unroll
        for (int off = 16; off; off >>= 1) {
            int o = __shfl_xor_sync(0xFFFFFFFFu, val, off);
            val = ismax ? max(val, o) : min(val, o);
        }
        if (lane == 0) { if (ismax) smax[d] = val; else smin[d] = val; }
    }
    __syncthreads();
    int m0 = smin[0], m1 = smin[1], m2 = smin[2];
    int M1 = smax[1] - m1, M2 = smax[2] - m2;

    unsigned long long e[IPT];
#pragma unroll
    for (int it = 0; it < IPT; it++) {
        int i = bib * BLK_ITEMS + w * (IPT * 32) + it * 32 + lane;
        int d0 = q0r[it] - m0, d1 = q1r[it] - m1, d2 = q2r[it] - m2;
        int s1 = (d0 & 1)        ? (M1 - d1) : d1;
        int s2 = ((d0 + d1) & 1) ? (M2 - d2) : d2;
        bool msk = (i < NLID) ? (lmask[(size_t)seg * NLID + i] != 0)
                              : (imask[(size_t)seg * NIMG + (i - NLID)] != 0);
        unsigned key = msk ? 0xFFFFFFu
                           : (((unsigned)d0 << 16) | ((unsigned)s1 << 8) | (unsigned)s2);
        e[it] = ((unsigned long long)key << 16) | (unsigned)i;
        atomicAdd(&hist[key & 255u], 1u);
    }
    __syncthreads();
    g_cnt0[seg * CNT_SEG + tid * NBLK_SEG + bib] = hist[tid];

    grid_barrier(base, 2);

    // ---- Phase C: pass 0 (entries already in registers) ----
    pass_body(e, g_cnt0 + seg * CNT_SEG, g_e1 + seg * NTOK,
              g_cnt1 + seg * CNT_SEG, 16, 24, bib, w, lane, tid, sbase, whist, wsum);

    grid_barrier(base, 3);

    // ---- Phase D: pass 1 ----
#pragma unroll
    for (int it = 0; it < IPT; it++)
        e[it] = __ldcg(&g_e1[seg * NTOK + bib * BLK_ITEMS + w * (IPT * 32) + it * 32 + lane]);
    pass_body(e, g_cnt1 + seg * CNT_SEG, g_e0 + seg * NTOK,
              g_cnt2 + seg * CNT_SEG, 24, 32, bib, w, lane, tid, sbase, whist, wsum);

    grid_barrier(base, 4);

    // ---- Phase E: pass 2 (final -> g_e1) ----
#pragma unroll
    for (int it = 0; it < IPT; it++)
        e[it] = __ldcg(&g_e0[seg * NTOK + bib * BLK_ITEMS + w * (IPT * 32) + it * 32 + lane]);
    pass_body(e, g_cnt2 + seg * CNT_SEG, g_e1 + seg * NTOK,
              nullptr, 32, 0, bib, w, lane, tid, sbase, whist, wsum);

    // advance base for next launch (all blocks passed barrier 4; no more arrivals)
    if (blk == 0 && tid == 0) g_base = base + 4u * NBLKS;
}

// ---------------- gather: 16 threads/row, 4 independent float4 each (MLP 4) ----------------
__global__ void gather_kernel(const float* __restrict__ lidar_tokens,
                              const float* __restrict__ img_tokens,
                              const unsigned char* __restrict__ lmask,
                              const unsigned char* __restrict__ imask,
                              float* __restrict__ out, int out_size) {
    int gid = blockIdx.x * blockDim.x + threadIdx.x;   // TOTAL*16 threads
    int r = gid >> 4;
    int c = gid & 15;
    if (r >= TOTAL) return;
    unsigned long long e = g_e1[r];
    int idx = (int)(e & 0xFFFFull);
    int b = r / NTOK;
    const float4* src;
    if (idx < NLID)
        src = (const float4*)(lidar_tokens + ((size_t)b * NLID + idx) * C);
    else
        src = (const float4*)(img_tokens + ((size_t)b * NIMG + (idx - NLID)) * C);
    float4* d = (float4*)out + (size_t)r * 64;
#pragma unroll
    for (int k = 0; k < 4; k++)
        d[c + 16 * k] = src[c + 16 * k];

    if (c == 0) {
        size_t idx_base  = (size_t)TOTAL * C;
        size_t mask_base = idx_base + TOTAL;
        out[idx_base + r] = (float)idx;
        bool m = (idx < NLID) ? (lmask[(size_t)b * NLID + idx] != 0)
                              : (imask[(size_t)b * NIMG + (idx - NLID)] != 0);
        out[mask_base + r] = m ? 1.0f : 0.0f;
        if (r == 0) {
            size_t tail = mask_base + TOTAL;
            if ((size_t)out_size >= tail + 2) {
                out[tail + 0] = 16384.0f;
                out[tail + 1] = 1.0f;
            }
        }
    }
}

// ---------------- launch ----------------
extern "C" void kernel_launch(void* const* d_in, const int* in_sizes, int n_in,
                              void* d_out, int out_size) {
    const float* lidar_tokens = (const float*)d_in[0];
    const float* lidar_coords = (const float*)d_in[1];
    const float* img_tokens   = (const float*)d_in[2];
    const float* img_kuvd     = (const float*)d_in[3];
    const float* Km           = (const float*)d_in[4];
    const float* Tm           = (const float*)d_in[5];
    const float* Rm           = (const float*)d_in[6];
    const float* ptrans       = (const float*)d_in[7];
    const unsigned char* lm   = (const unsigned char*)d_in[8];
    const unsigned char* im   = (const unsigned char*)d_in[9];
    float* out = (float*)d_out;

    mega_kernel<<<NBLKS, STHR>>>(lidar_coords, img_kuvd, Km, Tm, Rm, ptrans, lm, im);
    gather_kernel<<<(TOTAL * 16) / 256, 256>>>(lidar_tokens, img_tokens, lm, im,
                                               out, out_size);
}